// round 4
// baseline (speedup 1.0000x reference)
#include <cuda_runtime.h>
#include <cuda_bf16.h>
#include <math.h>

// DescriptorBuilder: periodic minimum-image descriptors (O(N^2) factorized).
// Radial:  q_r[i,k] = sum_j fc(r_ij) * r_ij^k, k=0..8
// Angular: q_ang[i,n,0] = S_n^2, S_n = sum_j fc r^n
//          q_ang[i,n,1] = |V_n|^2, V_n = sum_j fc r^(n-1) dr
//          q_ang[i,n,2] = 0.5*(3*||M_n||_F^2 - S_n^2), M_n = sum_j fc r^(n-2) dr(x)dr
//
// 256 threads/block, 2 atoms/block (4 warps each), 96 blocks = one wave.
// Direct global loads (no smem staging, no producer barrier). Split-butterfly
// warp reduction (71 shuffles vs 180), scatter to per-warp smem buffers
// (deterministic, no atomics), single __syncthreads, distributed epilogue.

#define BLOCK 256
#define RCUT 6.0f

__global__ void __launch_bounds__(BLOCK)
desc_kernel(const float* __restrict__ R,
            const float* __restrict__ box,
            float* __restrict__ out, int N)
{
    __shared__ float sred[2][4][36];   // [atom slot][sub-warp][36 partial sums]

    const int t    = threadIdx.x;
    const int lane = t & 31;
    const int warp = t >> 5;        // 0..7
    const int a    = warp >> 2;     // atom slot (0/1)
    const int sub  = warp & 3;      // j-range quarter
    const int i    = blockIdx.x * 2 + a;
    const bool valid = (i < N);

    // Box + inverse in registers (redundant per thread, cheap).
    float b[9];
#pragma unroll
    for (int k = 0; k < 9; k++) b[k] = __ldg(box + k);

    const bool diag = (b[1] == 0.f && b[2] == 0.f && b[3] == 0.f &&
                       b[5] == 0.f && b[6] == 0.f && b[7] == 0.f);

    const float det =
        b[0] * (b[4] * b[8] - b[5] * b[7]) -
        b[1] * (b[3] * b[8] - b[5] * b[6]) +
        b[2] * (b[3] * b[7] - b[4] * b[6]);
    const float idet = 1.0f / det;
    float inv[9];
    inv[0] = (b[4] * b[8] - b[5] * b[7]) * idet;
    inv[1] = (b[2] * b[7] - b[1] * b[8]) * idet;
    inv[2] = (b[1] * b[5] - b[2] * b[4]) * idet;
    inv[3] = (b[5] * b[6] - b[3] * b[8]) * idet;
    inv[4] = (b[0] * b[8] - b[2] * b[6]) * idet;
    inv[5] = (b[2] * b[3] - b[0] * b[5]) * idet;
    inv[6] = (b[3] * b[7] - b[4] * b[6]) * idet;
    inv[7] = (b[1] * b[6] - b[0] * b[7]) * idet;
    inv[8] = (b[0] * b[4] - b[1] * b[3]) * idet;

    const float PI_OVER_RC = 3.14159265358979323846f / RCUT;

    // Accumulators: [0..8] radial (S_n = acc[n]); [9..17] V_n; [18..35] M_n.
    float acc[36];
#pragma unroll
    for (int k = 0; k < 36; k++) acc[k] = 0.0f;

    if (valid) {
        const float rix = __ldg(R + 3 * i + 0);
        const float riy = __ldg(R + 3 * i + 1);
        const float riz = __ldg(R + 3 * i + 2);

#pragma unroll 2
        for (int j = lane + 32 * sub; j < N; j += 128) {
            if (j == i) continue;
            // Cartesian displacement, then minimum image via fractional round.
            float cx = rix - __ldg(R + 3 * j + 0);
            float cy = riy - __ldg(R + 3 * j + 1);
            float cz = riz - __ldg(R + 3 * j + 2);
            float dx, dy, dz;
            if (diag) {
                float f0 = rintf(inv[0] * cx);
                float f1 = rintf(inv[4] * cy);
                float f2 = rintf(inv[8] * cz);
                dx = cx - b[0] * f0;
                dy = cy - b[4] * f1;
                dz = cz - b[8] * f2;
            } else {
                float f0 = rintf(inv[0] * cx + inv[1] * cy + inv[2] * cz);
                float f1 = rintf(inv[3] * cx + inv[4] * cy + inv[5] * cz);
                float f2 = rintf(inv[6] * cx + inv[7] * cy + inv[8] * cz);
                dx = cx - (b[0] * f0 + b[1] * f1 + b[2] * f2);
                dy = cy - (b[3] * f0 + b[4] * f1 + b[5] * f2);
                dz = cz - (b[6] * f0 + b[7] * f1 + b[8] * f2);
            }
            float r2 = dx * dx + dy * dy + dz * dz;
            float invr = rsqrtf(r2);
            float r = r2 * invr;
            if (r >= RCUT) continue;   // fc exactly 0 there

            float fc = 0.5f * __cosf(r * PI_OVER_RC) + 0.5f;

            // Radial moments fc * r^k, k = 0..8 (log-depth powers)
            float rr2 = r * r;
            float rr3 = rr2 * r;
            float rr4 = rr2 * rr2;
            float fcr4 = fc * rr4;
            acc[0] += fc;
            acc[1] += fc * r;
            acc[2] += fc * rr2;
            acc[3] += fc * rr3;
            acc[4] += fcr4;
            acc[5] += fcr4 * r;
            acc[6] += fcr4 * rr2;
            acc[7] += fcr4 * rr3;
            acc[8] += fcr4 * rr4;

            // Angular weights: wv_n = fc r^(n-1), wm_n = fc r^(n-2)
            float wv0 = fc * invr;
            float wv2 = fc * r;
            float wm0 = wv0 * invr;
            float xx = dx * dx, xy = dx * dy, xz = dx * dz;
            float yy = dy * dy, yz = dy * dz, zz = dz * dz;

            acc[9]  += wv0 * dx;  acc[10] += wv0 * dy;  acc[11] += wv0 * dz;
            acc[12] += fc  * dx;  acc[13] += fc  * dy;  acc[14] += fc  * dz;
            acc[15] += wv2 * dx;  acc[16] += wv2 * dy;  acc[17] += wv2 * dz;

            acc[18] += wm0 * xx;  acc[19] += wm0 * xy;  acc[20] += wm0 * xz;
            acc[21] += wm0 * yy;  acc[22] += wm0 * yz;  acc[23] += wm0 * zz;
            acc[24] += wv0 * xx;  acc[25] += wv0 * xy;  acc[26] += wv0 * xz;
            acc[27] += wv0 * yy;  acc[28] += wv0 * yz;  acc[29] += wv0 * zz;
            acc[30] += fc  * xx;  acc[31] += fc  * xy;  acc[32] += fc  * xz;
            acc[33] += fc  * yy;  acc[34] += fc  * yz;  acc[35] += fc  * zz;
        }

        // ---- Split-butterfly warp reduction: 36 -> 18 -> 9 -> 5 -> 3 -> 2 ----
        // At each xor stage the value set is halved between lane groups.
        float v18[18];
        {
            const bool up = (lane & 16) != 0;
#pragma unroll
            for (int k = 0; k < 18; k++) {
                float lo = acc[k]      + __shfl_xor_sync(0xffffffffu, acc[k], 16);
                float hi = acc[18 + k] + __shfl_xor_sync(0xffffffffu, acc[18 + k], 16);
                v18[k] = up ? hi : lo;
            }
        }
        float v9[9];
        {
            const bool up = (lane & 8) != 0;
#pragma unroll
            for (int k = 0; k < 9; k++) {
                float lo = v18[k]     + __shfl_xor_sync(0xffffffffu, v18[k], 8);
                float hi = v18[9 + k] + __shfl_xor_sync(0xffffffffu, v18[9 + k], 8);
                v9[k] = up ? hi : lo;
            }
        }
        float v5[5];
        {
            const bool up = (lane & 4) != 0;
#pragma unroll
            for (int k = 0; k < 5; k++) {
                float lo = v9[k] + __shfl_xor_sync(0xffffffffu, v9[k], 4);
                float hi = 0.0f;
                if (k < 4)
                    hi = v9[5 + k] + __shfl_xor_sync(0xffffffffu, v9[5 + k], 4);
                v5[k] = up ? hi : lo;   // upper group has only 4 valid (slot 4 junk)
            }
        }
        float v3[3];
        {
            const bool up = (lane & 2) != 0;
#pragma unroll
            for (int k = 0; k < 3; k++) {
                float lo = v5[k] + __shfl_xor_sync(0xffffffffu, v5[k], 2);
                float hi = 0.0f;
                if (k < 2)
                    hi = v5[3 + k] + __shfl_xor_sync(0xffffffffu, v5[3 + k], 2);
                v3[k] = up ? hi : lo;
            }
        }
        float v2[2];
        {
            const bool up = (lane & 1) != 0;
#pragma unroll
            for (int k = 0; k < 2; k++) {
                float lo = v3[k] + __shfl_xor_sync(0xffffffffu, v3[k], 1);
                float hi = 0.0f;
                if (k < 1)
                    hi = v3[2] + __shfl_xor_sync(0xffffffffu, v3[2], 1);
                v2[k] = up ? hi : lo;
            }
        }

        // Scatter this warp's fully-reduced values into its private smem slot.
        const int b4 = (lane >> 4) & 1, b3 = (lane >> 3) & 1;
        const int b2 = (lane >> 2) & 1, b1 = (lane >> 1) & 1, b0 = lane & 1;
        const int gsize = b2 ? 4 : 5;            // 5-group or 4-group after stage 3
        const int off0  = b1 * 3 + b0 * 2;       // offset of v2[0] within the group
        const int base  = b4 * 18 + b3 * 9 + b2 * 5;
        if (off0 < gsize)                        sred[a][sub][base + off0]     = v2[0];
        if (b0 == 0 && off0 + 1 < gsize)         sred[a][sub][base + off0 + 1] = v2[1];
    }
    __syncthreads();

    // Epilogue: 18 lanes of the first warp of each atom pair combine + write.
    if (valid && sub == 0 && lane < 18) {
        const float* p0 = sred[a][0];
        const float* p1 = sred[a][1];
        const float* p2 = sred[a][2];
        const float* p3 = sred[a][3];
#define TOT(k) (p0[k] + p1[k] + p2[k] + p3[k])

        float* o = out + (size_t)i * 18;
        float val;
        if (lane < 9) {
            val = TOT(lane);
        } else {
            int idx = lane - 9;
            int n = idx / 3;
            int l = idx - 3 * n;
            float s = TOT(n);
            if (l == 0) {
                val = s * s;
            } else if (l == 1) {
                float vx = TOT(9 + 3 * n), vy = TOT(10 + 3 * n), vz = TOT(11 + 3 * n);
                val = vx * vx + vy * vy + vz * vz;
            } else {
                float m0 = TOT(18 + 6 * n), m1 = TOT(19 + 6 * n), m2 = TOT(20 + 6 * n);
                float m3 = TOT(21 + 6 * n), m4 = TOT(22 + 6 * n), m5 = TOT(23 + 6 * n);
                float frob = m0 * m0 + m3 * m3 + m5 * m5 +
                             2.0f * (m1 * m1 + m2 * m2 + m4 * m4);
                val = 0.5f * (3.0f * frob - s * s);
            }
        }
        o[lane] = val;
#undef TOT
    }
}

extern "C" void kernel_launch(void* const* d_in, const int* in_sizes, int n_in,
                              void* d_out, int out_size) {
    const float* R   = (const float*)d_in[0];   // [N,3] fp32
    // d_in[1] = Z (int32), unused by the reference math
    const float* box = (const float*)d_in[2];   // [3,3] fp32
    float* out = (float*)d_out;                 // [N,18] fp32
    const int N = in_sizes[0] / 3;
    const int blocks = (N + 1) / 2;             // 2 atoms per block
    desc_kernel<<<blocks, BLOCK>>>(R, box, out, N);
}